// round 11
// baseline (speedup 1.0000x reference)
#include <cuda_runtime.h>
#include <cuda_fp16.h>
#include <cstdint>

#define D 128
#define PITCH 136              // fp16 elems per smem row = 272 B
#define NTHREADS 512

static const int MAX_E = 800000;
static const int MAX_N = 50000;

// Q stored fp16, permuted within each 32-col warp block:
//   pos = nc + qid*8 + ni*2 + t   holds column  col = nc + ni*8 + qid*2 + t
// Phase 2 reads q for accumulator element (ni,qid,t) at exactly that pos.
__device__ __align__(16) __half g_Q[(size_t)MAX_E * D];   // 204.8 MB
__device__ float g_h[MAX_E];
__device__ float g_denom[MAX_N];

// ---------------------------------------------------------------------------
__device__ __forceinline__ void mma16816(float c[4], const uint32_t a[4],
                                         const uint32_t b0, const uint32_t b1) {
    asm volatile(
        "mma.sync.aligned.m16n8k16.row.col.f32.f16.f16.f32 "
        "{%0,%1,%2,%3}, {%4,%5,%6,%7}, {%8,%9}, {%0,%1,%2,%3};"
        : "+f"(c[0]), "+f"(c[1]), "+f"(c[2]), "+f"(c[3])
        : "r"(a[0]), "r"(a[1]), "r"(a[2]), "r"(a[3]), "r"(b0), "r"(b1));
}
__device__ __forceinline__ void ldmx4(uint32_t r[4], uint32_t addr) {
    asm volatile("ldmatrix.sync.aligned.m8n8.x4.shared.b16 {%0,%1,%2,%3}, [%4];"
                 : "=r"(r[0]), "=r"(r[1]), "=r"(r[2]), "=r"(r[3]) : "r"(addr));
}
__device__ __forceinline__ void cp16(uint32_t dst_smem, const void* src, int srcBytes) {
    asm volatile("cp.async.cg.shared.global [%0], [%1], 16, %2;"
                 :: "r"(dst_smem), "l"(src), "r"(srcBytes) : "memory");
}
__device__ __forceinline__ void cp_commit() {
    asm volatile("cp.async.commit_group;" ::: "memory");
}
__device__ __forceinline__ void cp_wait0() {
    asm volatile("cp.async.wait_group 0;" ::: "memory");
}

// Phase-1 SMEM layout
static constexpr int S1_RAW = 0;                          // 64 KB raw fp32 A
static constexpr int S1_A0  = 65536;
static constexpr int S1_A1  = S1_A0 + 128 * 272;
static constexpr int S1_W   = S1_A1 + 128 * 272;          // 128 x 272 (W1)
static constexpr int S1_B   = S1_W + 128 * 272;           // 128 fp32 (b1)
static constexpr int S1_TOTAL = S1_B + 512;               // 170496

// Phase-2 SMEM layout
static constexpr int S2_RAW = 0;                          // 64 KB raw fp32 A
static constexpr int S2_A   = 65536;                      // 128 x 272 fp16 A
static constexpr int S2_W   = S2_A + 128 * 272;           // 128 x 272 (W0)
static constexpr int S2_Q   = S2_W + 128 * 272;           // 128 x 264 (Q rows)
static constexpr int S2_S   = S2_Q + 128 * 264;           // 128 fp32 scores
static constexpr int S2_RV  = S2_S + 512;                 // 128 int rev
static constexpr int S2_DV  = S2_RV + 512;                // 128 int dest
static constexpr int S2_TOTAL = S2_DV + 512;              // 170496

// ---------------------------------------------------------------------------
// Phase 1: Q = M @ W1^T + b1 (fp16, permuted). Zeroes out[]/g_denom[].
// CTA tile 128 rows x 128 cols; 16 warps = 4(M,32) x 4(N,32).
// ---------------------------------------------------------------------------
__global__ __launch_bounds__(NTHREADS, 1) void gemm_q(
    const float* __restrict__ M,
    const float* __restrict__ W1, const float* __restrict__ b1,
    float* __restrict__ out, int outN,
    int E, int numTiles)
{
    extern __shared__ char sm[];
    float*  sRaw = (float*)(sm + S1_RAW);
    __half* sW   = (__half*)(sm + S1_W);
    float*  sBias = (float*)(sm + S1_B);
    const uint32_t smBase = (uint32_t)(uint64_t)__cvta_generic_to_shared(sm);
    const uint32_t rawBase = smBase + S1_RAW;

    const int tid  = threadIdx.x;
    const int wid  = tid >> 5;
    const int lane = tid & 31;
    const int gid  = lane >> 2;
    const int qid  = lane & 3;

    // first tile prefetch
    {
        long row0 = (long)blockIdx.x * 128;
        if (blockIdx.x < numTiles) {
            #pragma unroll
            for (int t = 0; t < 8; t++) {
                int chunk = tid + t * NTHREADS;
                int r = chunk >> 5;
                int sz = (row0 + r < (long)E) ? 16 : 0;
                cp16(rawBase + chunk * 16,
                     (const char*)M + (row0 * D + (chunk & 31) * 4 + (long)r * D) * 4, sz);
            }
        }
        cp_commit();
    }

    // zero out[] and g_denom[]
    {
        int gstride = gridDim.x * NTHREADS;
        int g0 = blockIdx.x * NTHREADS + tid;
        float4 z4 = make_float4(0.f, 0.f, 0.f, 0.f);
        int n4 = outN >> 2;
        for (int i = g0; i < n4; i += gstride) ((float4*)out)[i] = z4;
        for (int i = g0; i < MAX_N; i += gstride) g_denom[i] = 0.0f;
    }

    // convert W1
    for (int i = tid; i < 128 * D; i += NTHREADS) {
        int n = i >> 7, k = i & 127;
        sW[n * PITCH + k] = __float2half_rn(W1[i]);
    }
    if (tid < 128) sBias[tid] = b1[tid];

    const int mr = (wid >> 2) * 32;
    const int nc = (wid & 3) * 32;

    const int rr = lane & 7;
    const int j  = lane >> 3;
    const uint32_t aOff = (uint32_t)((mr + ((j & 1) << 3) + rr) * 272 + ((j >> 1) << 4));
    const uint32_t aAddr0 = smBase + S1_A0 + aOff;
    const uint32_t aAddr1 = smBase + S1_A1 + aOff;
    uint32_t bAddr[2];
    #pragma unroll
    for (int nip = 0; nip < 2; nip++)
        bAddr[nip] = smBase + S1_W
                   + (uint32_t)((nc + nip * 16 + ((j >> 1) << 3) + rr) * 272
                                + ((j & 1) << 4));

    __syncthreads();

    int buf = 0;
    for (int tile = blockIdx.x; tile < numTiles; tile += gridDim.x) {
        long row0 = (long)tile * 128;
        int next = tile + gridDim.x;
        __half* sA = (__half*)(sm + (buf ? S1_A1 : S1_A0));
        const uint32_t aBase = buf ? aAddr1 : aAddr0;

        cp_wait0();

        #pragma unroll
        for (int t = 0; t < 8; t++) {
            int idx4 = tid + t * NTHREADS;
            int r  = idx4 >> 5;
            int c  = (idx4 & 31) * 4;
            float4 v = *(const float4*)(sRaw + r * 128 + c);
            __half2 h01 = __floats2half2_rn(v.x, v.y);
            __half2 h23 = __floats2half2_rn(v.z, v.w);
            uint2 hv = make_uint2(*(uint32_t*)&h01, *(uint32_t*)&h23);
            *(uint2*)(sA + r * PITCH + c) = hv;
        }
        __syncthreads();

        if (next < numTiles) {
            long nrow0 = (long)next * 128;
            #pragma unroll
            for (int t = 0; t < 8; t++) {
                int chunk = tid + t * NTHREADS;
                int r = chunk >> 5;
                int sz = (nrow0 + r < (long)E) ? 16 : 0;
                cp16(rawBase + chunk * 16,
                     (const char*)M + (nrow0 * D + (chunk & 31) * 4 + (long)r * D) * 4, sz);
            }
        }
        cp_commit();

        float acc[2][4][4];
        #pragma unroll
        for (int mi = 0; mi < 2; mi++)
            #pragma unroll
            for (int ni = 0; ni < 4; ni++)
                #pragma unroll
                for (int r = 0; r < 4; r++) acc[mi][ni][r] = 0.0f;

        #pragma unroll
        for (int ks = 0; ks < 8; ks++) {
            const uint32_t ko = (uint32_t)(ks * 32);
            uint32_t a[2][4];
            ldmx4(a[0], aBase + ko);
            ldmx4(a[1], aBase + 16 * 272 + ko);
            uint32_t b[2][4];
            ldmx4(b[0], bAddr[0] + ko);
            ldmx4(b[1], bAddr[1] + ko);
            #pragma unroll
            for (int mi = 0; mi < 2; mi++) {
                mma16816(acc[mi][0], a[mi], b[0][0], b[0][1]);
                mma16816(acc[mi][1], a[mi], b[0][2], b[0][3]);
                mma16816(acc[mi][2], a[mi], b[1][0], b[1][1]);
                mma16816(acc[mi][3], a[mi], b[1][2], b[1][3]);
            }
        }

        // store permuted: thread's 8 halves contiguous at nc + qid*8
        #pragma unroll
        for (int mi = 0; mi < 2; mi++) {
            long rowA = row0 + mr + mi * 16 + gid;
            long rowB = rowA + 8;
            __half2 hA[4], hB[4];
            #pragma unroll
            for (int ni = 0; ni < 4; ni++) {
                int col = nc + ni * 8 + qid * 2;
                float bx = sBias[col], by = sBias[col + 1];
                hA[ni] = __floats2half2_rn(acc[mi][ni][0] + bx, acc[mi][ni][1] + by);
                hB[ni] = __floats2half2_rn(acc[mi][ni][2] + bx, acc[mi][ni][3] + by);
            }
            if (rowA < (long)E)
                *(uint4*)(g_Q + rowA * D + nc + qid * 8) = make_uint4(
                    *(uint32_t*)&hA[0], *(uint32_t*)&hA[1],
                    *(uint32_t*)&hA[2], *(uint32_t*)&hA[3]);
            if (rowB < (long)E)
                *(uint4*)(g_Q + rowB * D + nc + qid * 8) = make_uint4(
                    *(uint32_t*)&hB[0], *(uint32_t*)&hB[1],
                    *(uint32_t*)&hB[2], *(uint32_t*)&hB[3]);
        }
        buf ^= 1;
    }
}

// ---------------------------------------------------------------------------
// Phase 2: fused P-GEMM + edge pass. Per 128-row tile:
//   P = M_tile @ W0^T (accumulators only), gather Q[rev] rows to smem,
//   s = a . LReLU(P + b0 + Q), h = exp(s + ab), denom[dest] += h,
//   g_h = h, out[dest] += h * M_fp16 (A tile in smem).
// ---------------------------------------------------------------------------
__global__ __launch_bounds__(NTHREADS, 1) void fused_pe(
    const float* __restrict__ M,
    const float* __restrict__ W0, const float* __restrict__ b0,
    const float* __restrict__ a_w, const float* __restrict__ a_b,
    const int* __restrict__ rev, const int* __restrict__ dest,
    float* __restrict__ out, int E, int numTiles)
{
    extern __shared__ char sm[];
    float*  sRaw = (float*)(sm + S2_RAW);
    __half* sA   = (__half*)(sm + S2_A);
    __half* sW   = (__half*)(sm + S2_W);
    char*   sQ   = sm + S2_Q;        // 128 rows x 264 B (132 halves)
    float*  sS   = (float*)(sm + S2_S);
    int*    sRV  = (int*)(sm + S2_RV);
    int*    sDV  = (int*)(sm + S2_DV);
    const uint32_t smBase = (uint32_t)(uint64_t)__cvta_generic_to_shared(sm);
    const uint32_t rawBase = smBase + S2_RAW;

    const int tid  = threadIdx.x;
    const int wid  = tid >> 5;
    const int lane = tid & 31;
    const int gid  = lane >> 2;
    const int qid  = lane & 3;

    // first tile prefetch
    {
        long row0 = (long)blockIdx.x * 128;
        if (blockIdx.x < numTiles) {
            #pragma unroll
            for (int t = 0; t < 8; t++) {
                int chunk = tid + t * NTHREADS;
                int r = chunk >> 5;
                int sz = (row0 + r < (long)E) ? 16 : 0;
                cp16(rawBase + chunk * 16,
                     (const char*)M + (row0 * D + (chunk & 31) * 4 + (long)r * D) * 4, sz);
            }
        }
        cp_commit();
    }

    // convert W0
    for (int i = tid; i < 128 * D; i += NTHREADS) {
        int n = i >> 7, k = i & 127;
        sW[n * PITCH + k] = __float2half_rn(W0[i]);
    }

    const int mr = (wid >> 2) * 32;
    const int nc = (wid & 3) * 32;

    // loop-invariant a_w / b0 gathers at this thread's accumulator columns
    float aw[8], bw[8];
    #pragma unroll
    for (int ni = 0; ni < 4; ni++)
        #pragma unroll
        for (int t = 0; t < 2; t++) {
            int col = nc + ni * 8 + qid * 2 + t;
            aw[ni * 2 + t] = a_w[col];
            bw[ni * 2 + t] = b0[col];
        }
    const float ab = a_b[0];

    const int rr = lane & 7;
    const int j  = lane >> 3;
    const uint32_t aBase = smBase + S2_A
        + (uint32_t)((mr + ((j & 1) << 3) + rr) * 272 + ((j >> 1) << 4));
    uint32_t bAddr[2];
    #pragma unroll
    for (int nip = 0; nip < 2; nip++)
        bAddr[nip] = smBase + S2_W
                   + (uint32_t)((nc + nip * 16 + ((j >> 1) << 3) + rr) * 272
                                + ((j & 1) << 4));

    for (int tile = blockIdx.x; tile < numTiles; tile += gridDim.x) {
        long row0 = (long)tile * 128;
        int next = tile + gridDim.x;

        cp_wait0();

        // stage rev/dest, zero scores
        if (tid < 128) {
            long grow = row0 + tid;
            sRV[tid] = (grow < (long)E) ? rev[grow] : 0;
            sDV[tid] = (grow < (long)E) ? dest[grow] : 0;
            sS[tid] = 0.0f;
        }
        // convert raw fp32 -> fp16 A tile
        #pragma unroll
        for (int t = 0; t < 8; t++) {
            int idx4 = tid + t * NTHREADS;
            int r  = idx4 >> 5;
            int c  = (idx4 & 31) * 4;
            float4 v = *(const float4*)(sRaw + r * 128 + c);
            __half2 h01 = __floats2half2_rn(v.x, v.y);
            __half2 h23 = __floats2half2_rn(v.z, v.w);
            uint2 hv = make_uint2(*(uint32_t*)&h01, *(uint32_t*)&h23);
            *(uint2*)(sA + r * PITCH + c) = hv;
        }
        __syncthreads();   // #1: A16/rv/dv/s ready; raw free

        if (next < numTiles) {
            long nrow0 = (long)next * 128;
            #pragma unroll
            for (int t = 0; t < 8; t++) {
                int chunk = tid + t * NTHREADS;
                int r = chunk >> 5;
                int sz = (nrow0 + r < (long)E) ? 16 : 0;
                cp16(rawBase + chunk * 16,
                     (const char*)M + (nrow0 * D + (chunk & 31) * 4 + (long)r * D) * 4, sz);
            }
        }
        cp_commit();

        // gather Q rows for this tile (warp wid owns rows wid*8..wid*8+7)
        #pragma unroll
        for (int i = 0; i < 8; i++) {
            int rl = wid * 8 + i;
            long qrow = sRV[rl];
            uint2 v = ((const uint2*)(g_Q + qrow * D))[lane];
            *(uint2*)(sQ + rl * 264 + lane * 8) = v;
        }

        // MMA: P tile in accumulators
        float acc[2][4][4];
        #pragma unroll
        for (int mi = 0; mi < 2; mi++)
            #pragma unroll
            for (int ni = 0; ni < 4; ni++)
                #pragma unroll
                for (int r = 0; r < 4; r++) acc[mi][ni][r] = 0.0f;

        #pragma unroll
        for (int ks = 0; ks < 8; ks++) {
            const uint32_t ko = (uint32_t)(ks * 32);
            uint32_t a[2][4];
            ldmx4(a[0], aBase + ko);
            ldmx4(a[1], aBase + 16 * 272 + ko);
            uint32_t b[2][4];
            ldmx4(b[0], bAddr[0] + ko);
            ldmx4(b[1], bAddr[1] + ko);
            #pragma unroll
            for (int mi = 0; mi < 2; mi++) {
                mma16816(acc[mi][0], a[mi], b[0][0], b[0][1]);
                mma16816(acc[mi][1], a[mi], b[0][2], b[0][3]);
                mma16816(acc[mi][2], a[mi], b[1][0], b[1][1]);
                mma16816(acc[mi][3], a[mi], b[1][2], b[1][3]);
            }
        }
        __syncthreads();   // #2: Q smem complete (filled by all warps)

        // score partials: z = LReLU(P + b0 + q), dot with a_w
        #pragma unroll
        for (int mi = 0; mi < 2; mi++) {
            int rlA = mr + mi * 16 + gid;
            int rlB = rlA + 8;
            float pA = 0.f, pB = 0.f;
            #pragma unroll
            for (int ni = 0; ni < 4; ni++) {
                int qoff = (nc + qid * 8 + ni * 2) * 2;
                float2 fa = __half22float2(*(__half2*)(sQ + rlA * 264 + qoff));
                float2 fb = __half22float2(*(__half2*)(sQ + rlB * 264 + qoff));
                float z0 = acc[mi][ni][0] + bw[ni*2]   + fa.x; z0 = z0 > 0.f ? z0 : 0.2f * z0;
                float z1 = acc[mi][ni][1] + bw[ni*2+1] + fa.y; z1 = z1 > 0.f ? z1 : 0.2f * z1;
                float z2 = acc[mi][ni][2] + bw[ni*2]   + fb.x; z2 = z2 > 0.f ? z2 : 0.2f * z2;
                float z3 = acc[mi][ni][3] + bw[ni*2+1] + fb.y; z3 = z3 > 0.f ? z3 : 0.2f * z3;
                pA += aw[ni*2] * z0 + aw[ni*2+1] * z1;
                pB += aw[ni*2] * z2 + aw[ni*2+1] * z3;
            }
            pA += __shfl_xor_sync(0xffffffffu, pA, 1);
            pA += __shfl_xor_sync(0xffffffffu, pA, 2);
            pB += __shfl_xor_sync(0xffffffffu, pB, 1);
            pB += __shfl_xor_sync(0xffffffffu, pB, 2);
            if (qid == 0) {
                atomicAdd(&sS[rlA], pA);
                atomicAdd(&sS[rlB], pB);
            }
        }
        __syncthreads();   // #3: scores final

        // h + denom + scatter (warp wid owns rows wid*8..wid*8+7)
        #pragma unroll
        for (int i = 0; i < 8; i++) {
            int rl = wid * 8 + i;
            long grow = row0 + rl;
            if (grow >= (long)E) continue;
            float h = expf(sS[rl] + ab);
            int d = sDV[rl];
            if (lane == 0) {
                g_h[grow] = h;
                atomicAdd(&g_denom[d], h);
            }
            uint2 mh = *(uint2*)((char*)sA + rl * 272 + lane * 8);
            float2 m01 = __half22float2(*(__half2*)&mh.x);
            float2 m23 = __half22float2(*(__half2*)&mh.y);
            float* o = out + (long)d * D + lane * 4;
            asm volatile("red.global.add.v4.f32 [%0], {%1, %2, %3, %4};"
                         :: "l"(o), "f"(h * m01.x), "f"(h * m01.y),
                            "f"(h * m23.x), "f"(h * m23.y)
                         : "memory");
        }
        __syncthreads();   // #4: A16/sQ/sS free for next tile
    }
}

// ---------------------------------------------------------------------------
// K3: normalize out rows by denom and compute alpha = h / denom[dest].
// ---------------------------------------------------------------------------
__global__ __launch_bounds__(256) void normalize_kernel(
    const int* __restrict__ dest,
    float* __restrict__ out, float* __restrict__ alpha_out, int N, int E)
{
    int i = blockIdx.x * blockDim.x + threadIdx.x;
    int nOut = N * 32;
    if (i < nOut) {
        int n = i >> 5;
        float inv = 1.0f / g_denom[n];
        float4* p = (float4*)out + i;
        float4 v = *p;
        v.x *= inv; v.y *= inv; v.z *= inv; v.w *= inv;
        *p = v;
    } else if (i < nOut + E) {
        int e = i - nOut;
        alpha_out[e] = g_h[e] / g_denom[dest[e]];
    }
}

// ---------------------------------------------------------------------------
extern "C" void kernel_launch(void* const* d_in, const int* in_sizes, int n_in,
                              void* d_out, int out_size)
{
    const float* M    = (const float*)d_in[0];
    const int*   dest = (const int*)d_in[1];
    const int*   rev  = (const int*)d_in[2];
    int base = (n_in >= 10) ? 4 : 3;
    const float* W0   = (const float*)d_in[base + 0];
    const float* b0   = (const float*)d_in[base + 1];
    const float* W1   = (const float*)d_in[base + 2];
    const float* b1   = (const float*)d_in[base + 3];
    const float* a_w  = (const float*)d_in[base + 4];
    const float* a_b  = (const float*)d_in[base + 5];

    int E = in_sizes[1];
    int N = (out_size - E) / D;

    float* out   = (float*)d_out;
    float* alpha = (float*)d_out + (long)N * D;

    cudaFuncSetAttribute(gemm_q,
        cudaFuncAttributeMaxDynamicSharedMemorySize, S1_TOTAL);
    cudaFuncSetAttribute(fused_pe,
        cudaFuncAttributeMaxDynamicSharedMemorySize, S2_TOTAL);

    int numTiles = (E + 127) / 128;

    // Phase 1: Q GEMM (also zeroes out[]/denom)
    gemm_q<<<148, NTHREADS, S1_TOTAL>>>(M, W1, b1, out, N * D, E, numTiles);

    // Phase 2: fused P GEMM + edge pass
    fused_pe<<<148, NTHREADS, S2_TOTAL>>>(M, W0, b0, a_w, a_b, rev, dest,
                                          out, E, numTiles);

    // K3: normalize + alpha
    int totWork = N * 32 + E;
    normalize_kernel<<<(totWork + 255) / 256, 256>>>(dest, out, alpha, N, E);
}

// round 12
// speedup vs baseline: 1.3528x; 1.3528x over previous
#include <cuda_runtime.h>
#include <cuda_fp16.h>
#include <cstdint>

#define D 128
#define PITCH 136              // fp16 elems per smem row = 272 B
#define NTHREADS 512

static const int MAX_E = 800000;
static const int MAX_N = 50000;

// P/Q fp16, permuted per 64-col block: pos = qid*16 + ni*2 + t holds
// col = block*64 + ni*8 + qid*2 + t. Edge kernel gathers a_w inverse-permuted.
// g_M16: fp16 copy of M (row-major), written by gemm, read by edge scatter.
__device__ __align__(16) __half g_P[(size_t)MAX_E * D];    // 204.8 MB
__device__ __align__(16) __half g_Q[(size_t)MAX_E * D];    // 204.8 MB
__device__ __align__(16) __half g_M16[(size_t)MAX_E * D];  // 204.8 MB
__device__ float g_h[MAX_E];
__device__ float g_denom[MAX_N];

// SMEM layout (byte offsets)
static constexpr int SM_RAW  = 0;                         // 128 x 512 B raw fp32 A
static constexpr int SM_A0   = 65536;                     // 128 x 272 B fp16 A buf0
static constexpr int SM_A1   = SM_A0 + 128 * 272;         // buf1
static constexpr int SM_W    = SM_A1 + 128 * 272;         // 256 x 272 B
static constexpr int SM_BIAS = SM_W + 256 * 272;          // 256 fp32
static constexpr int SM_TOTAL = SM_BIAS + 1024;           // 205824

// ---------------------------------------------------------------------------
__device__ __forceinline__ void mma16816(float c[4], const uint32_t a[4],
                                         const uint32_t b0, const uint32_t b1) {
    asm volatile(
        "mma.sync.aligned.m16n8k16.row.col.f32.f16.f16.f32 "
        "{%0,%1,%2,%3}, {%4,%5,%6,%7}, {%8,%9}, {%0,%1,%2,%3};"
        : "+f"(c[0]), "+f"(c[1]), "+f"(c[2]), "+f"(c[3])
        : "r"(a[0]), "r"(a[1]), "r"(a[2]), "r"(a[3]), "r"(b0), "r"(b1));
}
__device__ __forceinline__ void ldmx4(uint32_t r[4], uint32_t addr) {
    asm volatile("ldmatrix.sync.aligned.m8n8.x4.shared.b16 {%0,%1,%2,%3}, [%4];"
                 : "=r"(r[0]), "=r"(r[1]), "=r"(r[2]), "=r"(r[3]) : "r"(addr));
}
__device__ __forceinline__ void cp16(uint32_t dst_smem, const void* src, int srcBytes) {
    asm volatile("cp.async.cg.shared.global [%0], [%1], 16, %2;"
                 :: "r"(dst_smem), "l"(src), "r"(srcBytes) : "memory");
}
__device__ __forceinline__ void cp_commit() {
    asm volatile("cp.async.commit_group;" ::: "memory");
}
__device__ __forceinline__ void cp_wait0() {
    asm volatile("cp.async.wait_group 0;" ::: "memory");
}
__device__ __forceinline__ void stg_cs_v4(void* p, uint4 v) {
    asm volatile("st.global.cs.v4.u32 [%0], {%1, %2, %3, %4};"
                 :: "l"(p), "r"(v.x), "r"(v.y), "r"(v.z), "r"(v.w) : "memory");
}

// ---------------------------------------------------------------------------
// K1: fp16 mma.sync GEMM, 512 threads, double-buffered A16, ldmatrix, permuted
// wide-store epilogue. Also writes g_M16 and zeroes out[]/g_denom[].
// [128 x 256] tile = M @ [W0;W1]^T + b.  P = cols 0..127, Q = cols 128..255.
// ---------------------------------------------------------------------------
__global__ __launch_bounds__(NTHREADS, 1) void gemm_mma(
    const float* __restrict__ M,
    const float* __restrict__ W0, const float* __restrict__ b0,
    const float* __restrict__ W1, const float* __restrict__ b1,
    float* __restrict__ out, int outN,
    int E, int numTiles)
{
    extern __shared__ char sm[];
    float*  sRaw = (float*)(sm + SM_RAW);
    __half* sW   = (__half*)(sm + SM_W);
    float*  sBias = (float*)(sm + SM_BIAS);
    const uint32_t smBase = (uint32_t)(uint64_t)__cvta_generic_to_shared(sm);
    const uint32_t rawBase = smBase + SM_RAW;

    const int tid  = threadIdx.x;
    const int wid  = tid >> 5;
    const int lane = tid & 31;
    const int gid  = lane >> 2;
    const int qid  = lane & 3;

    // Prologue: issue cp.async for the first tile FIRST
    {
        long row0 = (long)blockIdx.x * 128;
        if (blockIdx.x < numTiles) {
            #pragma unroll
            for (int t = 0; t < 8; t++) {
                int chunk = tid + t * NTHREADS;
                int r = chunk >> 5;
                int sz = (row0 + r < (long)E) ? 16 : 0;
                cp16(rawBase + chunk * 16,
                     (const char*)M + (row0 * D + (chunk & 31) * 4 + (long)r * D) * 4, sz);
            }
        }
        cp_commit();
    }

    // Zero out[] and g_denom[]
    {
        int gstride = gridDim.x * NTHREADS;
        int g0 = blockIdx.x * NTHREADS + tid;
        float4 z4 = make_float4(0.f, 0.f, 0.f, 0.f);
        int n4 = outN >> 2;
        for (int i = g0; i < n4; i += gstride) ((float4*)out)[i] = z4;
        for (int i = g0; i < MAX_N; i += gstride) g_denom[i] = 0.0f;
    }

    // Convert W once
    for (int i = tid; i < 256 * D; i += NTHREADS) {
        int n = i >> 7, k = i & 127;
        float w = (n < 128) ? W0[n * D + k] : W1[(n - 128) * D + k];
        sW[n * PITCH + k] = __float2half_rn(w);
    }
    if (tid < 256) sBias[tid] = (tid < 128) ? b0[tid] : b1[tid - 128];

    const int mr = (wid >> 2) * 32;
    const int nc = (wid & 3) * 64;
    const int blockQ = (nc >= 128);
    const int blk64  = (nc & 64) ? 1 : 0;

    const int rr = lane & 7;
    const int j  = lane >> 3;
    const uint32_t aOff = (uint32_t)((mr + ((j & 1) << 3) + rr) * 272 + ((j >> 1) << 4));
    const uint32_t aAddr0 = smBase + SM_A0 + aOff;
    const uint32_t aAddr1 = smBase + SM_A1 + aOff;
    uint32_t bAddr[4];
    #pragma unroll
    for (int nip = 0; nip < 4; nip++)
        bAddr[nip] = smBase + SM_W
                   + (uint32_t)((nc + nip * 16 + ((j >> 1) << 3) + rr) * 272
                                + ((j & 1) << 4));

    int buf = 0;
    for (int tile = blockIdx.x; tile < numTiles; tile += gridDim.x) {
        long row0 = (long)tile * 128;
        int next = tile + gridDim.x;
        __half* sA = (__half*)(sm + (buf ? SM_A1 : SM_A0));
        const uint32_t aBase = buf ? aAddr1 : aAddr0;

        cp_wait0();

        // Convert raw fp32 -> fp16: into smem A16[buf] AND g_M16 (coalesced)
        #pragma unroll
        for (int t = 0; t < 8; t++) {
            int idx4 = tid + t * NTHREADS;
            int r  = idx4 >> 5;
            int c  = (idx4 & 31) * 4;
            float4 v = *(const float4*)(sRaw + r * 128 + c);
            __half2 h01 = __floats2half2_rn(v.x, v.y);
            __half2 h23 = __floats2half2_rn(v.z, v.w);
            uint2 hv = make_uint2(*(uint32_t*)&h01, *(uint32_t*)&h23);
            *(uint2*)(sA + r * PITCH + c) = hv;
            if (row0 + r < (long)E)
                *(uint2*)(g_M16 + (row0 + r) * D + c) = hv;
        }
        __syncthreads();

        if (next < numTiles) {
            long nrow0 = (long)next * 128;
            #pragma unroll
            for (int t = 0; t < 8; t++) {
                int chunk = tid + t * NTHREADS;
                int r = chunk >> 5;
                int sz = (nrow0 + r < (long)E) ? 16 : 0;
                cp16(rawBase + chunk * 16,
                     (const char*)M + (nrow0 * D + (chunk & 31) * 4 + (long)r * D) * 4, sz);
            }
        }
        cp_commit();

        // Compute: warp tile 32x64 -> acc[2][8][4]
        float acc[2][8][4];
        #pragma unroll
        for (int mi = 0; mi < 2; mi++)
            #pragma unroll
            for (int ni = 0; ni < 8; ni++)
                #pragma unroll
                for (int r = 0; r < 4; r++) acc[mi][ni][r] = 0.0f;

        #pragma unroll
        for (int ks = 0; ks < 8; ks++) {
            const uint32_t ko = (uint32_t)(ks * 32);
            uint32_t a[2][4];
            ldmx4(a[0], aBase + ko);
            ldmx4(a[1], aBase + 16 * 272 + ko);
            uint32_t b[4][4];
            #pragma unroll
            for (int nip = 0; nip < 4; nip++)
                ldmx4(b[nip], bAddr[nip] + ko);

            #pragma unroll
            for (int mi = 0; mi < 2; mi++)
                #pragma unroll
                for (int nip = 0; nip < 4; nip++) {
                    mma16816(acc[mi][nip * 2 + 0], a[mi], b[nip][0], b[nip][1]);
                    mma16816(acc[mi][nip * 2 + 1], a[mi], b[nip][2], b[nip][3]);
                }
        }

        // Epilogue: + bias, permuted wide stores (P streaming, Q default)
        __half* gBase = blockQ ? g_Q : g_P;
        #pragma unroll
        for (int mi = 0; mi < 2; mi++) {
            long rowA = row0 + mr + mi * 16 + gid;
            long rowB = rowA + 8;
            __half2 hA[8], hB[8];
            #pragma unroll
            for (int ni = 0; ni < 8; ni++) {
                int col = nc + ni * 8 + qid * 2;
                float bx = sBias[col], by = sBias[col + 1];
                hA[ni] = __floats2half2_rn(acc[mi][ni][0] + bx, acc[mi][ni][1] + by);
                hB[ni] = __floats2half2_rn(acc[mi][ni][2] + bx, acc[mi][ni][3] + by);
            }
            if (rowA < (long)E) {
                __half* dst = gBase + rowA * D + blk64 * 64 + qid * 16;
                uint4 v0 = make_uint4(*(uint32_t*)&hA[0], *(uint32_t*)&hA[1],
                                      *(uint32_t*)&hA[2], *(uint32_t*)&hA[3]);
                uint4 v1 = make_uint4(*(uint32_t*)&hA[4], *(uint32_t*)&hA[5],
                                      *(uint32_t*)&hA[6], *(uint32_t*)&hA[7]);
                if (blockQ) { ((uint4*)dst)[0] = v0; ((uint4*)dst)[1] = v1; }
                else { stg_cs_v4(dst, v0); stg_cs_v4(dst + 8, v1); }
            }
            if (rowB < (long)E) {
                __half* dst = gBase + rowB * D + blk64 * 64 + qid * 16;
                uint4 v0 = make_uint4(*(uint32_t*)&hB[0], *(uint32_t*)&hB[1],
                                      *(uint32_t*)&hB[2], *(uint32_t*)&hB[3]);
                uint4 v1 = make_uint4(*(uint32_t*)&hB[4], *(uint32_t*)&hB[5],
                                      *(uint32_t*)&hB[6], *(uint32_t*)&hB[7]);
                if (blockQ) { ((uint4*)dst)[0] = v0; ((uint4*)dst)[1] = v1; }
                else { stg_cs_v4(dst, v0); stg_cs_v4(dst + 8, v1); }
            }
        }
        buf ^= 1;
    }
}

// ---------------------------------------------------------------------------
// K2: fused edge pass, 4 edges per warp. P/Q permuted; a_w gathered at
// inverse-permuted columns. M read as fp16 from g_M16 (half the bytes).
//   h = exp(a . LReLU(P[e] + Q[rev[e]]) + a_b)      (segment-max skipped)
//   denom[dest[e]] += h ; g_h[e] = h ; out[dest[e]] += h * M16[e]
// ---------------------------------------------------------------------------
__global__ __launch_bounds__(256) void edge_kernel(
    const int* __restrict__ rev, const int* __restrict__ dest,
    const float* __restrict__ a_w, const float* __restrict__ a_b,
    float* __restrict__ out, int E)
{
    const int warp = (blockIdx.x * blockDim.x + threadIdx.x) >> 5;
    const int lane = threadIdx.x & 31;
    const long e0 = (long)warp * 4;
    if (e0 >= E) return;

    // Inverse permutation of this lane's 4 positions p = lane*4 + {0..3}
    const int p0   = lane * 4;
    const int blk  = p0 >> 6;
    const int bb   = p0 & 63;
    const int c0   = blk * 64 + ((bb & 15) >> 1) * 8 + (bb >> 4) * 2;
    const float aw0 = a_w[c0],     aw1 = a_w[c0 + 1];
    const float aw2 = a_w[c0 + 8], aw3 = a_w[c0 + 9];

    int4 rv, dv;
    if (lane == 0) {
        rv = *(const int4*)(rev + e0);
        dv = *(const int4*)(dest + e0);
    }
    rv.x = __shfl_sync(0xffffffffu, rv.x, 0); rv.y = __shfl_sync(0xffffffffu, rv.y, 0);
    rv.z = __shfl_sync(0xffffffffu, rv.z, 0); rv.w = __shfl_sync(0xffffffffu, rv.w, 0);
    dv.x = __shfl_sync(0xffffffffu, dv.x, 0); dv.y = __shfl_sync(0xffffffffu, dv.y, 0);
    dv.z = __shfl_sync(0xffffffffu, dv.z, 0); dv.w = __shfl_sync(0xffffffffu, dv.w, 0);
    const int re[4] = {rv.x, rv.y, rv.z, rv.w};
    const int dd[4] = {dv.x, dv.y, dv.z, dv.w};

    const int nE = (int)(((long)E - e0) < 4 ? ((long)E - e0) : 4);

    uint2 pv[4], qv[4], mv[4];
    #pragma unroll
    for (int i = 0; i < 4; i++) {
        long e = (i < nE) ? (e0 + i) : e0;
        int r  = (i < nE) ? re[i] : re[0];
        pv[i] = ((const uint2*)g_P)[e * 32 + lane];
        qv[i] = ((const uint2*)g_Q)[(long)r * 32 + lane];
        mv[i] = ((const uint2*)g_M16)[e * 32 + lane];
    }
    const float ab = a_b[0];

    float part[4];
    #pragma unroll
    for (int i = 0; i < 4; i++) {
        float2 p01 = __half22float2(*(const __half2*)&pv[i].x);
        float2 p23 = __half22float2(*(const __half2*)&pv[i].y);
        float2 q01 = __half22float2(*(const __half2*)&qv[i].x);
        float2 q23 = __half22float2(*(const __half2*)&qv[i].y);
        float zx = p01.x + q01.x; zx = zx > 0.f ? zx : 0.2f * zx;
        float zy = p01.y + q01.y; zy = zy > 0.f ? zy : 0.2f * zy;
        float zz = p23.x + q23.x; zz = zz > 0.f ? zz : 0.2f * zz;
        float zw = p23.y + q23.y; zw = zw > 0.f ? zw : 0.2f * zw;
        part[i] = aw0 * zx + aw1 * zy + aw2 * zz + aw3 * zw;
    }

    #pragma unroll
    for (int off = 16; off; off >>= 1) {
        #pragma unroll
        for (int i = 0; i < 4; i++)
            part[i] += __shfl_xor_sync(0xffffffffu, part[i], off);
    }

    float h[4];
    #pragma unroll
    for (int i = 0; i < 4; i++) h[i] = expf(part[i] + ab);

    if (lane == 0)           { g_h[e0 + 0] = h[0]; atomicAdd(&g_denom[dd[0]], h[0]); }
    if (lane == 1 && nE > 1) { g_h[e0 + 1] = h[1]; atomicAdd(&g_denom[dd[1]], h[1]); }
    if (lane == 2 && nE > 2) { g_h[e0 + 2] = h[2]; atomicAdd(&g_denom[dd[2]], h[2]); }
    if (lane == 3 && nE > 3) { g_h[e0 + 3] = h[3]; atomicAdd(&g_denom[dd[3]], h[3]); }

    #pragma unroll
    for (int i = 0; i < 4; i++) {
        if (i < nE) {
            float2 m01 = __half22float2(*(const __half2*)&mv[i].x);
            float2 m23 = __half22float2(*(const __half2*)&mv[i].y);
            float* o = out + (long)dd[i] * D + lane * 4;
            asm volatile("red.global.add.v4.f32 [%0], {%1, %2, %3, %4};"
                         :: "l"(o), "f"(h[i] * m01.x), "f"(h[i] * m01.y),
                            "f"(h[i] * m23.x), "f"(h[i] * m23.y)
                         : "memory");
        }
    }
}

// ---------------------------------------------------------------------------
// K3: normalize out rows by denom and compute alpha = h / denom[dest].
// ---------------------------------------------------------------------------
__global__ __launch_bounds__(256) void normalize_kernel(
    const int* __restrict__ dest,
    float* __restrict__ out, float* __restrict__ alpha_out, int N, int E)
{
    int i = blockIdx.x * blockDim.x + threadIdx.x;
    int nOut = N * 32;
    if (i < nOut) {
        int n = i >> 5;
        float inv = 1.0f / g_denom[n];
        float4* p = (float4*)out + i;
        float4 v = *p;
        v.x *= inv; v.y *= inv; v.z *= inv; v.w *= inv;
        *p = v;
    } else if (i < nOut + E) {
        int e = i - nOut;
        alpha_out[e] = g_h[e] / g_denom[dest[e]];
    }
}

// ---------------------------------------------------------------------------
extern "C" void kernel_launch(void* const* d_in, const int* in_sizes, int n_in,
                              void* d_out, int out_size)
{
    const float* M    = (const float*)d_in[0];
    const int*   dest = (const int*)d_in[1];
    const int*   rev  = (const int*)d_in[2];
    int base = (n_in >= 10) ? 4 : 3;
    const float* W0   = (const float*)d_in[base + 0];
    const float* b0   = (const float*)d_in[base + 1];
    const float* W1   = (const float*)d_in[base + 2];
    const float* b1   = (const float*)d_in[base + 3];
    const float* a_w  = (const float*)d_in[base + 4];
    const float* a_b  = (const float*)d_in[base + 5];

    int E = in_sizes[1];
    int N = (out_size - E) / D;

    float* out   = (float*)d_out;
    float* alpha = (float*)d_out + (long)N * D;

    cudaFuncSetAttribute(gemm_mma,
        cudaFuncAttributeMaxDynamicSharedMemorySize, SM_TOTAL);

    // K1: GEMM (zeroes out[]/denom; writes P, Q, M16)
    int numTiles = (E + 127) / 128;
    gemm_mma<<<148, NTHREADS, SM_TOTAL>>>(M, W0, b0, W1, b1, out, N * D, E, numTiles);

    // K2: fused edge pass, 4 edges/warp
    long warps = ((long)E + 3) / 4;
    int blocks = (int)((warps + 7) / 8);
    edge_kernel<<<blocks, 256>>>(rev, dest, a_w, a_b, out, E);

    // K3: normalize + alpha
    int totWork = N * 32 + E;
    normalize_kernel<<<(totWork + 255) / 256, 256>>>(dest, out, alpha, N, E);
}

// round 13
// speedup vs baseline: 1.4441x; 1.0675x over previous
#include <cuda_runtime.h>
#include <cuda_fp16.h>
#include <cstdint>

#define D 128
#define PITCH 136              // fp16 elems per smem row = 272 B
#define NTHREADS 512

static const int MAX_E = 800000;
static const int MAX_N = 50000;

// P/Q fp16, permuted per 64-col block: pos = qid*16 + ni*2 + t holds
// col = block*64 + ni*8 + qid*2 + t. Edge kernel gathers a_w inverse-permuted.
// g_M16: fp16 copy of M (row-major), written by gemm, read by edge scatter.
__device__ __align__(16) __half g_P[(size_t)MAX_E * D];    // 204.8 MB
__device__ __align__(16) __half g_Q[(size_t)MAX_E * D];    // 204.8 MB
__device__ __align__(16) __half g_M16[(size_t)MAX_E * D];  // 204.8 MB
__device__ float g_h[MAX_E];
__device__ float g_denom[MAX_N];

// SMEM layout (byte offsets)
static constexpr int SM_RAW  = 0;                         // 128 x 512 B raw fp32 A
static constexpr int SM_A0   = 65536;                     // 128 x 272 B fp16 A buf0
static constexpr int SM_A1   = SM_A0 + 128 * 272;         // buf1
static constexpr int SM_W    = SM_A1 + 128 * 272;         // 256 x 272 B
static constexpr int SM_BIAS = SM_W + 256 * 272;          // 256 fp32
static constexpr int SM_TOTAL = SM_BIAS + 1024;           // 205824

// ---------------------------------------------------------------------------
__device__ __forceinline__ void mma16816(float c[4], const uint32_t a[4],
                                         const uint32_t b0, const uint32_t b1) {
    asm volatile(
        "mma.sync.aligned.m16n8k16.row.col.f32.f16.f16.f32 "
        "{%0,%1,%2,%3}, {%4,%5,%6,%7}, {%8,%9}, {%0,%1,%2,%3};"
        : "+f"(c[0]), "+f"(c[1]), "+f"(c[2]), "+f"(c[3])
        : "r"(a[0]), "r"(a[1]), "r"(a[2]), "r"(a[3]), "r"(b0), "r"(b1));
}
__device__ __forceinline__ void ldmx4(uint32_t r[4], uint32_t addr) {
    asm volatile("ldmatrix.sync.aligned.m8n8.x4.shared.b16 {%0,%1,%2,%3}, [%4];"
                 : "=r"(r[0]), "=r"(r[1]), "=r"(r[2]), "=r"(r[3]) : "r"(addr));
}
__device__ __forceinline__ void cp16(uint32_t dst_smem, const void* src, int srcBytes) {
    asm volatile("cp.async.cg.shared.global [%0], [%1], 16, %2;"
                 :: "r"(dst_smem), "l"(src), "r"(srcBytes) : "memory");
}
__device__ __forceinline__ void cp_commit() {
    asm volatile("cp.async.commit_group;" ::: "memory");
}
__device__ __forceinline__ void cp_wait0() {
    asm volatile("cp.async.wait_group 0;" ::: "memory");
}

// ---------------------------------------------------------------------------
// K1: fp16 mma.sync GEMM, 512 threads, double-buffered A16, ldmatrix, permuted
// wide-store epilogue. Writes g_M16 (post-barrier, overlapped with compute)
// and zeroes out[]/g_denom[] in its prologue.
// [128 x 256] tile = M @ [W0;W1]^T + b.  P = cols 0..127, Q = cols 128..255.
// ---------------------------------------------------------------------------
__global__ __launch_bounds__(NTHREADS, 1) void gemm_mma(
    const float* __restrict__ M,
    const float* __restrict__ W0, const float* __restrict__ b0,
    const float* __restrict__ W1, const float* __restrict__ b1,
    float* __restrict__ out, int outN,
    int E, int numTiles)
{
    extern __shared__ char sm[];
    float*  sRaw = (float*)(sm + SM_RAW);
    __half* sW   = (__half*)(sm + SM_W);
    float*  sBias = (float*)(sm + SM_BIAS);
    const uint32_t smBase = (uint32_t)(uint64_t)__cvta_generic_to_shared(sm);
    const uint32_t rawBase = smBase + SM_RAW;

    const int tid  = threadIdx.x;
    const int wid  = tid >> 5;
    const int lane = tid & 31;
    const int gid  = lane >> 2;
    const int qid  = lane & 3;

    // Prologue: issue cp.async for the first tile FIRST
    {
        long row0 = (long)blockIdx.x * 128;
        if (blockIdx.x < numTiles) {
            #pragma unroll
            for (int t = 0; t < 8; t++) {
                int chunk = tid + t * NTHREADS;
                int r = chunk >> 5;
                int sz = (row0 + r < (long)E) ? 16 : 0;
                cp16(rawBase + chunk * 16,
                     (const char*)M + (row0 * D + (chunk & 31) * 4 + (long)r * D) * 4, sz);
            }
        }
        cp_commit();
    }

    // Zero out[] and g_denom[]
    {
        int gstride = gridDim.x * NTHREADS;
        int g0 = blockIdx.x * NTHREADS + tid;
        float4 z4 = make_float4(0.f, 0.f, 0.f, 0.f);
        int n4 = outN >> 2;
        for (int i = g0; i < n4; i += gstride) ((float4*)out)[i] = z4;
        for (int i = g0; i < MAX_N; i += gstride) g_denom[i] = 0.0f;
    }

    // Convert W once
    for (int i = tid; i < 256 * D; i += NTHREADS) {
        int n = i >> 7, k = i & 127;
        float w = (n < 128) ? W0[n * D + k] : W1[(n - 128) * D + k];
        sW[n * PITCH + k] = __float2half_rn(w);
    }
    if (tid < 256) sBias[tid] = (tid < 128) ? b0[tid] : b1[tid - 128];

    const int mr = (wid >> 2) * 32;
    const int nc = (wid & 3) * 64;
    const int blockQ = (nc >= 128);
    const int blk64  = (nc & 64) ? 1 : 0;

    const int rr = lane & 7;
    const int j  = lane >> 3;
    const uint32_t aOff = (uint32_t)((mr + ((j & 1) << 3) + rr) * 272 + ((j >> 1) << 4));
    const uint32_t aAddr0 = smBase + SM_A0 + aOff;
    const uint32_t aAddr1 = smBase + SM_A1 + aOff;
    uint32_t bAddr[4];
    #pragma unroll
    for (int nip = 0; nip < 4; nip++)
        bAddr[nip] = smBase + SM_W
                   + (uint32_t)((nc + nip * 16 + ((j >> 1) << 3) + rr) * 272
                                + ((j & 1) << 4));

    int buf = 0;
    for (int tile = blockIdx.x; tile < numTiles; tile += gridDim.x) {
        long row0 = (long)tile * 128;
        int next = tile + gridDim.x;
        __half* sA = (__half*)(sm + (buf ? SM_A1 : SM_A0));
        const uint32_t aBase = buf ? aAddr1 : aAddr0;

        cp_wait0();

        // Convert raw fp32 -> fp16 into smem A16[buf]; keep values in regs
        uint2 hv[8];
        #pragma unroll
        for (int t = 0; t < 8; t++) {
            int idx4 = tid + t * NTHREADS;
            int r  = idx4 >> 5;
            int c  = (idx4 & 31) * 4;
            float4 v = *(const float4*)(sRaw + r * 128 + c);
            __half2 h01 = __floats2half2_rn(v.x, v.y);
            __half2 h23 = __floats2half2_rn(v.z, v.w);
            hv[t] = make_uint2(*(uint32_t*)&h01, *(uint32_t*)&h23);
            *(uint2*)(sA + r * PITCH + c) = hv[t];
        }
        __syncthreads();

        // g_M16 writes AFTER the barrier: off the critical path, drain
        // through the store buffer while the MMA loop runs.
        #pragma unroll
        for (int t = 0; t < 8; t++) {
            int idx4 = tid + t * NTHREADS;
            int r  = idx4 >> 5;
            int c  = (idx4 & 31) * 4;
            if (row0 + r < (long)E)
                *(uint2*)(g_M16 + (row0 + r) * D + c) = hv[t];
        }

        if (next < numTiles) {
            long nrow0 = (long)next * 128;
            #pragma unroll
            for (int t = 0; t < 8; t++) {
                int chunk = tid + t * NTHREADS;
                int r = chunk >> 5;
                int sz = (nrow0 + r < (long)E) ? 16 : 0;
                cp16(rawBase + chunk * 16,
                     (const char*)M + (nrow0 * D + (chunk & 31) * 4 + (long)r * D) * 4, sz);
            }
        }
        cp_commit();

        // Compute: warp tile 32x64 -> acc[2][8][4]
        float acc[2][8][4];
        #pragma unroll
        for (int mi = 0; mi < 2; mi++)
            #pragma unroll
            for (int ni = 0; ni < 8; ni++)
                #pragma unroll
                for (int r = 0; r < 4; r++) acc[mi][ni][r] = 0.0f;

        #pragma unroll
        for (int ks = 0; ks < 8; ks++) {
            const uint32_t ko = (uint32_t)(ks * 32);
            uint32_t a[2][4];
            ldmx4(a[0], aBase + ko);
            ldmx4(a[1], aBase + 16 * 272 + ko);
            uint32_t b[4][4];
            #pragma unroll
            for (int nip = 0; nip < 4; nip++)
                ldmx4(b[nip], bAddr[nip] + ko);

            #pragma unroll
            for (int mi = 0; mi < 2; mi++)
                #pragma unroll
                for (int nip = 0; nip < 4; nip++) {
                    mma16816(acc[mi][nip * 2 + 0], a[mi], b[nip][0], b[nip][1]);
                    mma16816(acc[mi][nip * 2 + 1], a[mi], b[nip][2], b[nip][3]);
                }
        }

        // Epilogue: + bias, permuted wide stores
        __half* gBase = blockQ ? g_Q : g_P;
        #pragma unroll
        for (int mi = 0; mi < 2; mi++) {
            long rowA = row0 + mr + mi * 16 + gid;
            long rowB = rowA + 8;
            __half2 hA[8], hB[8];
            #pragma unroll
            for (int ni = 0; ni < 8; ni++) {
                int col = nc + ni * 8 + qid * 2;
                float bx = sBias[col], by = sBias[col + 1];
                hA[ni] = __floats2half2_rn(acc[mi][ni][0] + bx, acc[mi][ni][1] + by);
                hB[ni] = __floats2half2_rn(acc[mi][ni][2] + bx, acc[mi][ni][3] + by);
            }
            if (rowA < (long)E) {
                __half* dst = gBase + rowA * D + blk64 * 64 + qid * 16;
                ((uint4*)dst)[0] = make_uint4(
                    *(uint32_t*)&hA[0], *(uint32_t*)&hA[1],
                    *(uint32_t*)&hA[2], *(uint32_t*)&hA[3]);
                ((uint4*)dst)[1] = make_uint4(
                    *(uint32_t*)&hA[4], *(uint32_t*)&hA[5],
                    *(uint32_t*)&hA[6], *(uint32_t*)&hA[7]);
            }
            if (rowB < (long)E) {
                __half* dst = gBase + rowB * D + blk64 * 64 + qid * 16;
                ((uint4*)dst)[0] = make_uint4(
                    *(uint32_t*)&hB[0], *(uint32_t*)&hB[1],
                    *(uint32_t*)&hB[2], *(uint32_t*)&hB[3]);
                ((uint4*)dst)[1] = make_uint4(
                    *(uint32_t*)&hB[4], *(uint32_t*)&hB[5],
                    *(uint32_t*)&hB[6], *(uint32_t*)&hB[7]);
            }
        }
        buf ^= 1;
    }
}

// ---------------------------------------------------------------------------
// K2: fused edge pass, 4 edges per warp. P/Q permuted; a_w gathered at
// inverse-permuted columns. M read as fp16 from g_M16 (half the bytes).
//   h = exp(a . LReLU(P[e] + Q[rev[e]]) + a_b)      (segment-max skipped)
//   denom[dest[e]] += h ; g_h[e] = h ; out[dest[e]] += h * M16[e]
// ---------------------------------------------------------------------------
__global__ __launch_bounds__(256) void edge_kernel(
    const int* __restrict__ rev, const int* __restrict__ dest,
    const float* __restrict__ a_w, const float* __restrict__ a_b,
    float* __restrict__ out, int E)
{
    const int warp = (blockIdx.x * blockDim.x + threadIdx.x) >> 5;
    const int lane = threadIdx.x & 31;
    const long e0 = (long)warp * 4;
    if (e0 >= E) return;

    // Inverse permutation of this lane's 4 positions p = lane*4 + {0..3}
    const int p0   = lane * 4;
    const int blk  = p0 >> 6;
    const int bb   = p0 & 63;
    const int c0   = blk * 64 + ((bb & 15) >> 1) * 8 + (bb >> 4) * 2;
    const float aw0 = a_w[c0],     aw1 = a_w[c0 + 1];
    const float aw2 = a_w[c0 + 8], aw3 = a_w[c0 + 9];

    int4 rv, dv;
    if (lane == 0) {
        rv = *(const int4*)(rev + e0);
        dv = *(const int4*)(dest + e0);
    }
    rv.x = __shfl_sync(0xffffffffu, rv.x, 0); rv.y = __shfl_sync(0xffffffffu, rv.y, 0);
    rv.z = __shfl_sync(0xffffffffu, rv.z, 0); rv.w = __shfl_sync(0xffffffffu, rv.w, 0);
    dv.x = __shfl_sync(0xffffffffu, dv.x, 0); dv.y = __shfl_sync(0xffffffffu, dv.y, 0);
    dv.z = __shfl_sync(0xffffffffu, dv.z, 0); dv.w = __shfl_sync(0xffffffffu, dv.w, 0);
    const int re[4] = {rv.x, rv.y, rv.z, rv.w};
    const int dd[4] = {dv.x, dv.y, dv.z, dv.w};

    const int nE = (int)(((long)E - e0) < 4 ? ((long)E - e0) : 4);

    uint2 pv[4], qv[4], mv[4];
    #pragma unroll
    for (int i = 0; i < 4; i++) {
        long e = (i < nE) ? (e0 + i) : e0;
        int r  = (i < nE) ? re[i] : re[0];
        pv[i] = ((const uint2*)g_P)[e * 32 + lane];
        qv[i] = ((const uint2*)g_Q)[(long)r * 32 + lane];
        mv[i] = ((const uint2*)g_M16)[e * 32 + lane];
    }
    const float ab = a_b[0];

    float part[4];
    #pragma unroll
    for (int i = 0; i < 4; i++) {
        float2 p01 = __half22float2(*(const __half2*)&pv[i].x);
        float2 p23 = __half22float2(*(const __half2*)&pv[i].y);
        float2 q01 = __half22float2(*(const __half2*)&qv[i].x);
        float2 q23 = __half22float2(*(const __half2*)&qv[i].y);
        float zx = p01.x + q01.x; zx = zx > 0.f ? zx : 0.2f * zx;
        float zy = p01.y + q01.y; zy = zy > 0.f ? zy : 0.2f * zy;
        float zz = p23.x + q23.x; zz = zz > 0.f ? zz : 0.2f * zz;
        float zw = p23.y + q23.y; zw = zw > 0.f ? zw : 0.2f * zw;
        part[i] = aw0 * zx + aw1 * zy + aw2 * zz + aw3 * zw;
    }

    #pragma unroll
    for (int off = 16; off; off >>= 1) {
        #pragma unroll
        for (int i = 0; i < 4; i++)
            part[i] += __shfl_xor_sync(0xffffffffu, part[i], off);
    }

    float h[4];
    #pragma unroll
    for (int i = 0; i < 4; i++) h[i] = expf(part[i] + ab);

    if (lane == 0)           { g_h[e0 + 0] = h[0]; atomicAdd(&g_denom[dd[0]], h[0]); }
    if (lane == 1 && nE > 1) { g_h[e0 + 1] = h[1]; atomicAdd(&g_denom[dd[1]], h[1]); }
    if (lane == 2 && nE > 2) { g_h[e0 + 2] = h[2]; atomicAdd(&g_denom[dd[2]], h[2]); }
    if (lane == 3 && nE > 3) { g_h[e0 + 3] = h[3]; atomicAdd(&g_denom[dd[3]], h[3]); }

    #pragma unroll
    for (int i = 0; i < 4; i++) {
        if (i < nE) {
            float2 m01 = __half22float2(*(const __half2*)&mv[i].x);
            float2 m23 = __half22float2(*(const __half2*)&mv[i].y);
            float* o = out + (long)dd[i] * D + lane * 4;
            asm volatile("red.global.add.v4.f32 [%0], {%1, %2, %3, %4};"
                         :: "l"(o), "f"(h[i] * m01.x), "f"(h[i] * m01.y),
                            "f"(h[i] * m23.x), "f"(h[i] * m23.y)
                         : "memory");
        }
    }
}

// ---------------------------------------------------------------------------
// K3: normalize out rows by denom and compute alpha = h / denom[dest].
// ---------------------------------------------------------------------------
__global__ __launch_bounds__(256) void normalize_kernel(
    const int* __restrict__ dest,
    float* __restrict__ out, float* __restrict__ alpha_out, int N, int E)
{
    int i = blockIdx.x * blockDim.x + threadIdx.x;
    int nOut = N * 32;
    if (i < nOut) {
        int n = i >> 5;
        float inv = 1.0f / g_denom[n];
        float4* p = (float4*)out + i;
        float4 v = *p;
        v.x *= inv; v.y *= inv; v.z *= inv; v.w *= inv;
        *p = v;
    } else if (i < nOut + E) {
        int e = i - nOut;
        alpha_out[e] = g_h[e] / g_denom[dest[e]];
    }
}

// ---------------------------------------------------------------------------
extern "C" void kernel_launch(void* const* d_in, const int* in_sizes, int n_in,
                              void* d_out, int out_size)
{
    const float* M    = (const float*)d_in[0];
    const int*   dest = (const int*)d_in[1];
    const int*   rev  = (const int*)d_in[2];
    int base = (n_in >= 10) ? 4 : 3;
    const float* W0   = (const float*)d_in[base + 0];
    const float* b0   = (const float*)d_in[base + 1];
    const float* W1   = (const float*)d_in[base + 2];
    const float* b1   = (const float*)d_in[base + 3];
    const float* a_w  = (const float*)d_in[base + 4];
    const float* a_b  = (const float*)d_in[base + 5];

    int E = in_sizes[1];
    int N = (out_size - E) / D;

    float* out   = (float*)d_out;
    float* alpha = (float*)d_out + (long)N * D;

    cudaFuncSetAttribute(gemm_mma,
        cudaFuncAttributeMaxDynamicSharedMemorySize, SM_TOTAL);

    // K1: GEMM (zeroes out[]/denom; writes P, Q, M16)
    int numTiles = (E + 127) / 128;
    gemm_mma<<<148, NTHREADS, SM_TOTAL>>>(M, W0, b0, W1, b1, out, N * D, E, numTiles);

    // K2: fused edge pass, 4 edges/warp
    long warps = ((long)E + 3) / 4;
    int blocks = (int)((warps + 7) / 8);
    edge_kernel<<<blocks, 256>>>(rev, dest, a_w, a_b, out, E);

    // K3: normalize + alpha
    int totWork = N * 32 + E;
    normalize_kernel<<<(totWork + 255) / 256, 256>>>(dest, out, alpha, N, E);
}